// round 10
// baseline (speedup 1.0000x reference)
#include <cuda_runtime.h>
#include <cuda_fp16.h>

// HDBLUT 2x superresolution, GB300 sm_103a. Round 10: SINGLE KERNEL.
//  - contiguous per-CTA tile bands; each CTA nibble-packs its own <=14
//    image rows (reflection baked) into smem next to the 96KB fp16 LUT
//  - no prelude kernel, no global packed image, one graph node
//  - R7 gather core (row-pair, interleaved pixels), 2 CTAs/SM x 640 thr

#define NN 2048
#define NTILES (1024 * 64)        // row-pairs x 32-col tiles
#define THREADS 640
#define WARPS_PER_CTA (THREADS / 32)
#define LUT_E (3 * 4096)
#define PSTRIDE 260               // words per packed row (257 used)
#define PWORDS 257
#define MAXROWS 14                // max rows a 216-tile band touches (incl halo)
#define SMEM_BYTES (LUT_E * 8 + MAXROWS * PSTRIDE * 4)

__device__ __forceinline__ int refl(int t) {
    t = (t < 0) ? -t : t;
    return (t >= NN) ? (2 * NN - 2 - t) : t;
}

__device__ __forceinline__ __half2 u2h(unsigned u) {
    return *reinterpret_cast<__half2*>(&u);
}

__global__ __launch_bounds__(THREADS, 2)
void hdblut_fused(const int* __restrict__ img,
                  const float4* __restrict__ wlut,
                  float2* __restrict__ out)
{
    extern __shared__ unsigned char smem_raw[];
    uint2*    slut  = reinterpret_cast<uint2*>(smem_raw);
    unsigned* spimg = reinterpret_cast<unsigned*>(smem_raw + LUT_E * 8);

    // ---- CTA band: tiles [t0, t1) ----
    const int t0 = (int)((unsigned long long)blockIdx.x       * NTILES / gridDim.x);
    const int t1 = (int)((unsigned long long)(blockIdx.x + 1) * NTILES / gridDim.x);
    const int rp_lo  = t0 >> 6;
    const int rp_hi  = (t1 - 1) >> 6;
    const int row_lo = 2 * rp_lo - 2;                  // may be negative
    const int nrows  = 2 * (rp_hi - rp_lo) + 6;        // <= MAXROWS

    // ---- fill fp16 LUT (1/3 folded) ----
    for (int i = threadIdx.x; i < LUT_E; i += THREADS) {
        float4 v = __ldg(wlut + i);
        const float s = 1.0f / 3.0f;
        __half2 lo = __floats2half2_rn(v.x * s, v.y * s);
        __half2 hi = __floats2half2_rn(v.z * s, v.w * s);
        uint2 u;
        u.x = *reinterpret_cast<unsigned*>(&lo);
        u.y = *reinterpret_cast<unsigned*>(&hi);
        slut[i] = u;
    }

    // ---- pack this band's rows (reflection baked in both axes) ----
    for (int i = threadIdx.x; i < nrows * PWORDS; i += THREADS) {
        const int lr = i / PWORDS;
        const int wi = i - lr * PWORDS;
        const int* row = img + (size_t)refl(row_lo + lr) * NN;
        const int cb = wi * 8 - 2;
        unsigned val = 0;
        if (cb >= 0 && cb + 7 < NN) {
            #pragma unroll
            for (int j = 0; j < 8; j++)
                val |= (unsigned)(row[cb + j] & 15) << (4 * j);
        } else {
            #pragma unroll
            for (int j = 0; j < 8; j++)
                val |= (unsigned)(row[refl(cb + j)] & 15) << (4 * j);
        }
        spimg[lr * PSTRIDE + wi] = val;
    }
    __syncthreads();

    const int warp = threadIdx.x >> 5;
    const int lane = threadIdx.x & 31;

    for (int t = t0 + warp; t < t1; t += WARPS_PER_CTA) {
        const int I  = (t >> 6) << 1;       // low-res row pair (I, I+1)
        const int Jb = (t & 63) << 5;

        // 6 packed rows I-2..I+3 from smem; nibble j of rc[i] = col J-2+j
        unsigned rc[6];
        {
            const int pos = Jb + lane;
            const int wi  = pos >> 3;
            const int sh  = (pos & 7) * 4;
            const unsigned* pr = spimg + (I - 2 - row_lo) * PSTRIDE + wi;
            #pragma unroll
            for (int i = 0; i < 6; i++) {
                unsigned w0 = pr[i * PSTRIDE];
                unsigned w1 = pr[i * PSTRIDE + 1];
                rc[i] = __funnelshift_r(w0, w1, sh);
            }
        }

        float acc[2][4];
        #pragma unroll
        for (int ro = 0; ro < 2; ro++)
            acc[ro][0] = acc[ro][1] = acc[ro][2] = acc[ro][3] = 0.f;

        #define NIB(i, j)  ((int)((rc[(i)] >> (4 * (j))) & 15u))
        #define GIDX(ro, k, bx, by, cx, cy) \
            ((k) * 4096 + a8 + (NIB(2 + (ro) + (bx), 2 + (by)) << 4) \
                            +  NIB(2 + (ro) + (cx), 2 + (cy)))

        // One rotation = 3 gathers (k=0,1,2) sharing a permutation:
        //   r=0: (0,1,2,3)  r=1: (2,0,3,1)  r=2: (3,2,1,0)  r=3: (1,3,0,2)
        #define ROT3(ro, b0x,b0y,c0x,c0y, b1x,b1y,c1x,c1y, b2x,b2y,c2x,c2y, \
                     i00,i01,i10,i11) do {                                  \
            uint2 h0 = slut[GIDX(ro, 0, b0x,b0y, c0x,c0y)];                 \
            uint2 h1 = slut[GIDX(ro, 1, b1x,b1y, c1x,c1y)];                 \
            uint2 h2 = slut[GIDX(ro, 2, b2x,b2y, c2x,c2y)];                 \
            __half2 sA = __hadd2(__hadd2(u2h(h0.x), u2h(h1.x)), u2h(h2.x)); \
            __half2 sB = __hadd2(__hadd2(u2h(h0.y), u2h(h1.y)), u2h(h2.y)); \
            float2 fA = __half22float2(sA);                                 \
            float2 fB = __half22float2(sB);                                 \
            float fv[4] = {fA.x, fA.y, fB.x, fB.y};                         \
            acc[ro][0] += fv[i00]; acc[ro][1] += fv[i01];                   \
            acc[ro][2] += fv[i10]; acc[ro][3] += fv[i11];                   \
        } while (0)

        #pragma unroll
        for (int ro = 0; ro < 2; ro++) {
            const int a8 = NIB(2 + ro, 2) << 8;
            // r = 0: offsets as-is
            ROT3(ro,  0, 1,  0, 2,   1, 1,  2, 2,   1, 2,  2, 1,  0,1,2,3);
            // r = 1: (x,y) -> (y,-x)
            ROT3(ro,  1, 0,  2, 0,   1,-1,  2,-2,   2,-1,  1,-2,  2,0,3,1);
            // r = 2: (x,y) -> (-x,-y)
            ROT3(ro,  0,-1,  0,-2,  -1,-1, -2,-2,  -1,-2, -2,-1,  3,2,1,0);
            // r = 3: (x,y) -> (-y,x)
            ROT3(ro, -1, 0, -2, 0,  -1, 1, -2, 2,  -2, 1, -1, 2,  1,3,0,2);
        }

        #undef ROT3
        #undef GIDX
        #undef NIB

        const int J = Jb + lane;
        const size_t base = (size_t)(2 * I) * 2048 + J;
        out[base        ] = make_float2(acc[0][0], acc[0][1]);
        out[base + 2048 ] = make_float2(acc[0][2], acc[0][3]);
        out[base + 4096 ] = make_float2(acc[1][0], acc[1][1]);
        out[base + 6144 ] = make_float2(acc[1][2], acc[1][3]);
    }
}

extern "C" void kernel_launch(void* const* d_in, const int* in_sizes, int n_in,
                              void* d_out, int out_size)
{
    const int*    img  = (const int*)d_in[0];
    const float4* wlut = (const float4*)d_in[1];
    float2*       out  = (float2*)d_out;

    int sms = 0;
    cudaDeviceGetAttribute(&sms, cudaDevAttrMultiProcessorCount, 0);
    if (sms <= 0) sms = 148;

    cudaFuncSetAttribute(hdblut_fused,
                         cudaFuncAttributeMaxDynamicSharedMemorySize, SMEM_BYTES);
    hdblut_fused<<<2 * sms, THREADS, SMEM_BYTES>>>(img, wlut, out);
}

// round 11
// speedup vs baseline: 1.0054x; 1.0054x over previous
#include <cuda_runtime.h>
#include <cuda_fp16.h>

// HDBLUT 2x superresolution, GB300 sm_103a. Round 11: one kernel.
//  Phase A: each CTA converts a LUT slice (fp32->fp16, 1/3 folded) to g_lut
//           and nibble-packs a disjoint slice of image rows to g_pimg.
//  Ticket barrier (monotonic, graph-replay-safe; all 304 CTAs co-resident).
//  Phase B: exact R7 main loop — 96KB smem LUT fill from g_lut, warp-cyclic
//           row-pair gathers, 2 CTAs/SM x 640 threads.

#define NN 2048
#define NTILES (1024 * 64)        // row-pairs x 32-col tiles
#define THREADS 640
#define WARPS_PER_CTA (THREADS / 32)
#define LUT_E (3 * 4096)
#define PSTRIDE 260
#define PWORDS 257
#define SMEM_BYTES (LUT_E * 8)

__device__ __align__(16) uint2 g_lut[LUT_E];   // half4 per entry, 96 KB
__device__ unsigned g_pimg[NN * PSTRIDE];      // nibble-packed image
__device__ unsigned g_bar = 0;                 // monotonic barrier ticket

__device__ __forceinline__ int refl(int t) {
    t = (t < 0) ? -t : t;
    return (t >= NN) ? (2 * NN - 2 - t) : t;
}

__device__ __forceinline__ __half2 u2h(unsigned u) {
    return *reinterpret_cast<__half2*>(&u);
}

__global__ __launch_bounds__(THREADS, 2)
void hdblut_all(const int* __restrict__ img,
                const float4* __restrict__ wlut,
                float2* __restrict__ out)
{
    extern __shared__ uint2 slut[];   // 96 KB fp16 LUT

    const int G = gridDim.x;

    // ---- Phase A1: LUT convert slice (first 12288 global threads) ----
    {
        int idx = blockIdx.x * THREADS + threadIdx.x;
        if (idx < LUT_E) {
            float4 v = __ldg(wlut + idx);
            const float s = 1.0f / 3.0f;
            __half2 lo = __floats2half2_rn(v.x * s, v.y * s);
            __half2 hi = __floats2half2_rn(v.z * s, v.w * s);
            uint2 u;
            u.x = *reinterpret_cast<unsigned*>(&lo);
            u.y = *reinterpret_cast<unsigned*>(&hi);
            g_lut[idx] = u;
        }
    }

    // ---- Phase A2: pack image rows slice [r0, r1) ----
    {
        const int r0 = (int)((unsigned long long)blockIdx.x       * NN / G);
        const int r1 = (int)((unsigned long long)(blockIdx.x + 1) * NN / G);
        for (int i = threadIdx.x; i < (r1 - r0) * PWORDS; i += THREADS) {
            const int lr = i / PWORDS;
            const int wi = i - lr * PWORDS;
            const int  r  = r0 + lr;
            const int* row = img + (size_t)r * NN;
            const int cb = wi * 8 - 2;
            unsigned val = 0;
            if (cb >= 0 && cb + 7 < NN) {
                #pragma unroll
                for (int j = 0; j < 8; j++)
                    val |= (unsigned)(__ldg(row + cb + j) & 15) << (4 * j);
            } else {
                #pragma unroll
                for (int j = 0; j < 8; j++)
                    val |= (unsigned)(__ldg(row + refl(cb + j)) & 15) << (4 * j);
            }
            g_pimg[(size_t)r * PSTRIDE + wi] = val;
        }
    }

    // ---- Global ticket barrier (replay-safe: counter monotonic) ----
    __threadfence();
    __syncthreads();
    if (threadIdx.x == 0) {
        unsigned ticket = atomicAdd(&g_bar, 1u) + 1u;
        unsigned target = ((ticket + G - 1u) / G) * G;
        while (*(volatile unsigned*)&g_bar < target) { }
    }
    __syncthreads();
    __threadfence();

    // ---- Phase B: fill smem LUT from g_lut (fp16, uint4) ----
    {
        uint4*       s4 = reinterpret_cast<uint4*>(slut);
        const uint4* g4 = reinterpret_cast<const uint4*>(g_lut);
        for (int i = threadIdx.x; i < LUT_E / 2; i += THREADS)
            s4[i] = g4[i];
    }
    __syncthreads();

    const int warp = threadIdx.x >> 5;
    const int lane = threadIdx.x & 31;
    const int gwarp  = blockIdx.x * WARPS_PER_CTA + warp;
    const int nwarps = G * WARPS_PER_CTA;

    for (int t = gwarp; t < NTILES; t += nwarps) {
        const int I  = (t >> 6) << 1;       // low-res row pair (I, I+1)
        const int Jb = (t & 63) << 5;

        // 6 packed rows I-2..I+3; nibble j of rc[i] = img col J-2+j (J=Jb+lane)
        unsigned rc[6];
        {
            const int pos = Jb + lane;
            const int wi  = pos >> 3;
            const int sh  = (pos & 7) * 4;
            #pragma unroll
            for (int i = 0; i < 6; i++) {
                const unsigned* pr = g_pimg + (size_t)refl(I - 2 + i) * PSTRIDE + wi;
                unsigned w0 = __ldg(pr);
                unsigned w1 = __ldg(pr + 1);
                rc[i] = __funnelshift_r(w0, w1, sh);
            }
        }

        float acc[2][4];
        #pragma unroll
        for (int ro = 0; ro < 2; ro++)
            acc[ro][0] = acc[ro][1] = acc[ro][2] = acc[ro][3] = 0.f;

        #define NIB(i, j)  ((int)((rc[(i)] >> (4 * (j))) & 15u))
        #define GIDX(ro, k, bx, by, cx, cy) \
            ((k) * 4096 + a8 + (NIB(2 + (ro) + (bx), 2 + (by)) << 4) \
                            +  NIB(2 + (ro) + (cx), 2 + (cy)))

        // One rotation = 3 gathers (k=0,1,2) sharing a permutation:
        //   r=0: (0,1,2,3)  r=1: (2,0,3,1)  r=2: (3,2,1,0)  r=3: (1,3,0,2)
        #define ROT3(ro, b0x,b0y,c0x,c0y, b1x,b1y,c1x,c1y, b2x,b2y,c2x,c2y, \
                     i00,i01,i10,i11) do {                                  \
            uint2 h0 = slut[GIDX(ro, 0, b0x,b0y, c0x,c0y)];                 \
            uint2 h1 = slut[GIDX(ro, 1, b1x,b1y, c1x,c1y)];                 \
            uint2 h2 = slut[GIDX(ro, 2, b2x,b2y, c2x,c2y)];                 \
            __half2 sA = __hadd2(__hadd2(u2h(h0.x), u2h(h1.x)), u2h(h2.x)); \
            __half2 sB = __hadd2(__hadd2(u2h(h0.y), u2h(h1.y)), u2h(h2.y)); \
            float2 fA = __half22float2(sA);                                 \
            float2 fB = __half22float2(sB);                                 \
            float fv[4] = {fA.x, fA.y, fB.x, fB.y};                         \
            acc[ro][0] += fv[i00]; acc[ro][1] += fv[i01];                   \
            acc[ro][2] += fv[i10]; acc[ro][3] += fv[i11];                   \
        } while (0)

        #pragma unroll
        for (int ro = 0; ro < 2; ro++) {
            const int a8 = NIB(2 + ro, 2) << 8;
            // r = 0: offsets as-is
            ROT3(ro,  0, 1,  0, 2,   1, 1,  2, 2,   1, 2,  2, 1,  0,1,2,3);
            // r = 1: (x,y) -> (y,-x)
            ROT3(ro,  1, 0,  2, 0,   1,-1,  2,-2,   2,-1,  1,-2,  2,0,3,1);
            // r = 2: (x,y) -> (-x,-y)
            ROT3(ro,  0,-1,  0,-2,  -1,-1, -2,-2,  -1,-2, -2,-1,  3,2,1,0);
            // r = 3: (x,y) -> (-y,x)
            ROT3(ro, -1, 0, -2, 0,  -1, 1, -2, 2,  -2, 1, -1, 2,  1,3,0,2);
        }

        #undef ROT3
        #undef GIDX
        #undef NIB

        const int J = Jb + lane;
        const size_t base = (size_t)(2 * I) * 2048 + J;
        out[base        ] = make_float2(acc[0][0], acc[0][1]);
        out[base + 2048 ] = make_float2(acc[0][2], acc[0][3]);
        out[base + 4096 ] = make_float2(acc[1][0], acc[1][1]);
        out[base + 6144 ] = make_float2(acc[1][2], acc[1][3]);
    }
}

extern "C" void kernel_launch(void* const* d_in, const int* in_sizes, int n_in,
                              void* d_out, int out_size)
{
    const int*    img  = (const int*)d_in[0];
    const float4* wlut = (const float4*)d_in[1];
    float2*       out  = (float2*)d_out;

    int sms = 0;
    cudaDeviceGetAttribute(&sms, cudaDevAttrMultiProcessorCount, 0);
    if (sms <= 0) sms = 148;

    cudaFuncSetAttribute(hdblut_all,
                         cudaFuncAttributeMaxDynamicSharedMemorySize, SMEM_BYTES);
    hdblut_all<<<2 * sms, THREADS, SMEM_BYTES>>>(img, wlut, out);
}

// round 12
// speedup vs baseline: 1.0603x; 1.0546x over previous
#include <cuda_runtime.h>
#include <cuda_fp16.h>

// HDBLUT 2x superresolution, GB300 sm_103a. Round 12:
//  R7 structure (prelude pack+convert kernel, row-pair main at 2x640),
//  with byte-offset gather addressing: nibbles extracted pre-scaled
//  (a<<11, b<<7, c<<3), one IADD3 per gather, k*32768 in the LDS immediate.

#define NN 2048
#define NTILES (1024 * 64)        // row-pairs x 32-col tiles
#define THREADS 640
#define WARPS_PER_CTA (THREADS / 32)
#define LUT_E (3 * 4096)
#define PSTRIDE 260
#define PWORDS 257
#define SMEM_BYTES (LUT_E * 8)

__device__ __align__(16) uint2 g_lut[LUT_E];   // half4 per entry, 96 KB
__device__ unsigned g_pimg[NN * PSTRIDE];      // nibble-packed image

__device__ __forceinline__ int refl(int t) {
    t = (t < 0) ? -t : t;
    return (t >= NN) ? (2 * NN - 2 - t) : t;
}

__device__ __forceinline__ __half2 u2h(unsigned u) {
    return *reinterpret_cast<__half2*>(&u);
}

// blocks 0..2047: pack one image row each (int4 loads via smem staging)
// blocks 2048..: convert LUT float4 -> half4 (1/3 folded)
__global__ void hdblut_prelude(const int* __restrict__ img,
                               const float4* __restrict__ w)
{
    __shared__ int srow[2056];
    const int tid = threadIdx.x;

    if (blockIdx.x < NN) {
        const int r = blockIdx.x;
        const int4* row4 = reinterpret_cast<const int4*>(img + (size_t)r * NN);
        #pragma unroll
        for (int k = 0; k < 2; k++) {
            int i = tid + k * 256;
            int4 v = __ldg(row4 + i);
            srow[2 + i * 4 + 0] = v.x;
            srow[2 + i * 4 + 1] = v.y;
            srow[2 + i * 4 + 2] = v.z;
            srow[2 + i * 4 + 3] = v.w;
        }
        __syncthreads();
        if (tid == 0) {
            srow[0] = srow[4];
            srow[1] = srow[3];
            #pragma unroll
            for (int i = 0; i < 6; i++)
                srow[2050 + i] = srow[2048 - i];
        }
        __syncthreads();
        for (int wi = tid; wi < PWORDS; wi += 256) {
            const int* s = srow + wi * 8;
            unsigned val = 0;
            #pragma unroll
            for (int j = 0; j < 8; j++)
                val |= (unsigned)(s[j] & 15) << (4 * j);
            g_pimg[(size_t)r * PSTRIDE + wi] = val;
        }
    } else {
        int gid = (blockIdx.x - NN) * blockDim.x + tid;
        if (gid < LUT_E) {
            float4 v = __ldg(w + gid);
            const float s = 1.0f / 3.0f;
            __half2 lo = __floats2half2_rn(v.x * s, v.y * s);
            __half2 hi = __floats2half2_rn(v.z * s, v.w * s);
            uint2 u;
            u.x = *reinterpret_cast<unsigned*>(&lo);
            u.y = *reinterpret_cast<unsigned*>(&hi);
            g_lut[gid] = u;
        }
    }
}

__global__ __launch_bounds__(THREADS, 2)
void hdblut_main(float2* __restrict__ out)
{
    extern __shared__ uint2 slut[];   // 96 KB fp16 LUT

    {
        uint4*       s4 = reinterpret_cast<uint4*>(slut);
        const uint4* g4 = reinterpret_cast<const uint4*>(g_lut);
        for (int i = threadIdx.x; i < LUT_E / 2; i += THREADS)
            s4[i] = g4[i];
    }
    __syncthreads();

    const char* lutb = reinterpret_cast<const char*>(slut);
    const int warp = threadIdx.x >> 5;
    const int lane = threadIdx.x & 31;
    const int gwarp  = blockIdx.x * WARPS_PER_CTA + warp;
    const int nwarps = gridDim.x * WARPS_PER_CTA;

    for (int t = gwarp; t < NTILES; t += nwarps) {
        const int I  = (t >> 6) << 1;       // low-res row pair (I, I+1)
        const int Jb = (t & 63) << 5;

        // 6 packed rows I-2..I+3; nibble j of rc[i] = img col J-2+j (J=Jb+lane)
        unsigned rc[6];
        {
            const int pos = Jb + lane;
            const int wi  = pos >> 3;
            const int sh  = (pos & 7) * 4;
            #pragma unroll
            for (int i = 0; i < 6; i++) {
                const unsigned* pr = g_pimg + (size_t)refl(I - 2 + i) * PSTRIDE + wi;
                unsigned w0 = __ldg(pr);
                unsigned w1 = __ldg(pr + 1);
                rc[i] = __funnelshift_r(w0, w1, sh);
            }
        }

        float acc[2][4];
        #pragma unroll
        for (int ro = 0; ro < 2; ro++)
            acc[ro][0] = acc[ro][1] = acc[ro][2] = acc[ro][3] = 0.f;

        // Pre-scaled nibble extraction: value<<tt, one SHF + one LOP3
        // (shift amount and mask are compile-time constants).
        #define EX(v, jj, tt) \
            (((4*(jj) >= (tt)) ? ((v) >> (4*(jj) - (tt)))               \
                               : ((v) << ((tt) - 4*(jj)))) & (15u << (tt)))

        // Gather byte offset: a<<11 (+k*32768 const) + b<<7 + c<<3 -> IADD3
        #define GOFF(ro, k, bx, by, cx, cy)                              \
            (a11 + (unsigned)((k) * 32768) +                             \
             EX(rc[2 + (ro) + (bx)], 2 + (by), 7) +                      \
             EX(rc[2 + (ro) + (cx)], 2 + (cy), 3))

        #define ROT3(ro, b0x,b0y,c0x,c0y, b1x,b1y,c1x,c1y, b2x,b2y,c2x,c2y, \
                     i00,i01,i10,i11) do {                                  \
            uint2 h0 = *reinterpret_cast<const uint2*>(                     \
                           lutb + GOFF(ro, 0, b0x,b0y, c0x,c0y));           \
            uint2 h1 = *reinterpret_cast<const uint2*>(                     \
                           lutb + GOFF(ro, 1, b1x,b1y, c1x,c1y));           \
            uint2 h2 = *reinterpret_cast<const uint2*>(                     \
                           lutb + GOFF(ro, 2, b2x,b2y, c2x,c2y));           \
            __half2 sA = __hadd2(__hadd2(u2h(h0.x), u2h(h1.x)), u2h(h2.x)); \
            __half2 sB = __hadd2(__hadd2(u2h(h0.y), u2h(h1.y)), u2h(h2.y)); \
            float2 fA = __half22float2(sA);                                 \
            float2 fB = __half22float2(sB);                                 \
            float fv[4] = {fA.x, fA.y, fB.x, fB.y};                         \
            acc[ro][0] += fv[i00]; acc[ro][1] += fv[i01];                   \
            acc[ro][2] += fv[i10]; acc[ro][3] += fv[i11];                   \
        } while (0)

        #pragma unroll
        for (int ro = 0; ro < 2; ro++) {
            // a nibble (row 2+ro, col 2, bits 8..11) pre-scaled to <<11
            const unsigned a11 = (rc[2 + ro] << 3) & (15u << 11);
            // r = 0: offsets as-is       perm (0,1,2,3)
            ROT3(ro,  0, 1,  0, 2,   1, 1,  2, 2,   1, 2,  2, 1,  0,1,2,3);
            // r = 1: (x,y)->(y,-x)       perm (2,0,3,1)
            ROT3(ro,  1, 0,  2, 0,   1,-1,  2,-2,   2,-1,  1,-2,  2,0,3,1);
            // r = 2: (x,y)->(-x,-y)      perm (3,2,1,0)
            ROT3(ro,  0,-1,  0,-2,  -1,-1, -2,-2,  -1,-2, -2,-1,  3,2,1,0);
            // r = 3: (x,y)->(-y,x)       perm (1,3,0,2)
            ROT3(ro, -1, 0, -2, 0,  -1, 1, -2, 2,  -2, 1, -1, 2,  1,3,0,2);
        }

        #undef ROT3
        #undef GOFF
        #undef EX

        const int J = Jb + lane;
        const size_t base = (size_t)(2 * I) * 2048 + J;
        out[base        ] = make_float2(acc[0][0], acc[0][1]);
        out[base + 2048 ] = make_float2(acc[0][2], acc[0][3]);
        out[base + 4096 ] = make_float2(acc[1][0], acc[1][1]);
        out[base + 6144 ] = make_float2(acc[1][2], acc[1][3]);
    }
}

extern "C" void kernel_launch(void* const* d_in, const int* in_sizes, int n_in,
                              void* d_out, int out_size)
{
    const int*    img  = (const int*)d_in[0];
    const float4* wlut = (const float4*)d_in[1];
    float2*       out  = (float2*)d_out;

    int sms = 0;
    cudaDeviceGetAttribute(&sms, cudaDevAttrMultiProcessorCount, 0);
    if (sms <= 0) sms = 148;

    hdblut_prelude<<<NN + (LUT_E + 255) / 256, 256>>>(img, wlut);

    cudaFuncSetAttribute(hdblut_main,
                         cudaFuncAttributeMaxDynamicSharedMemorySize, SMEM_BYTES);
    hdblut_main<<<2 * sms, THREADS, SMEM_BYTES>>>(out);
}